// round 1
// baseline (speedup 1.0000x reference)
#include <cuda_runtime.h>
#include <math.h>

// Problem constants
#define PB 2
#define PS 2048
#define PE 1024
#define PH 16
#define PD 64
#define PBS (PB * PS)   // 4096 rows

// Scratch (allocation-free rule: __device__ globals)
__device__ float g_Q[(size_t)PB * PS * PE];
__device__ float g_K[(size_t)PB * PS * PE];
__device__ float g_V[(size_t)PB * PS * PE];
__device__ float g_AO[(size_t)PB * PS * PE];

// ---------------------------------------------------------------------------
// GEMM: C[M,N] = A[M,K] @ W[K,N] + bias[N]
// 64x64 block tile, 256 threads, 4x4 per-thread micro-tile, BK=16
// ---------------------------------------------------------------------------
#define GBM 64
#define GBN 64
#define GBK 16

__global__ __launch_bounds__(256) void gemm_bias_kernel(
    const float* __restrict__ A, const float* __restrict__ W,
    const float* __restrict__ bias, float* __restrict__ C,
    int M, int N, int K)
{
    __shared__ float As[GBK][GBM + 4];   // row stride 68 floats = 272B (16B aligned)
    __shared__ float Ws[GBK][GBN];

    const int tid = threadIdx.x;
    const int tx = tid & 15;   // col group 0..15
    const int ty = tid >> 4;   // row group 0..15

    const int row0 = blockIdx.y * GBM;
    const int col0 = blockIdx.x * GBN;

    // A-tile load mapping: one float4 per thread along K, transpose into smem
    const int a_m  = tid >> 2;          // 0..63
    const int a_k4 = (tid & 3) << 2;    // 0,4,8,12
    // W-tile load mapping: one float4 per thread along N (coalesced)
    const int w_k  = tid >> 4;          // 0..15
    const int w_n4 = (tid & 15) << 2;   // 0..60

    float acc[4][4] = {};

    for (int k0 = 0; k0 < K; k0 += GBK) {
        float4 av = *reinterpret_cast<const float4*>(
            &A[(size_t)(row0 + a_m) * K + k0 + a_k4]);
        As[a_k4 + 0][a_m] = av.x;
        As[a_k4 + 1][a_m] = av.y;
        As[a_k4 + 2][a_m] = av.z;
        As[a_k4 + 3][a_m] = av.w;

        *reinterpret_cast<float4*>(&Ws[w_k][w_n4]) =
            *reinterpret_cast<const float4*>(
                &W[(size_t)(k0 + w_k) * N + col0 + w_n4]);
        __syncthreads();

#pragma unroll
        for (int kk = 0; kk < GBK; ++kk) {
            float4 a4 = *reinterpret_cast<const float4*>(&As[kk][ty << 2]);
            float4 b4 = *reinterpret_cast<const float4*>(&Ws[kk][tx << 2]);
            float ar[4] = {a4.x, a4.y, a4.z, a4.w};
            float br[4] = {b4.x, b4.y, b4.z, b4.w};
#pragma unroll
            for (int i = 0; i < 4; ++i)
#pragma unroll
                for (int j = 0; j < 4; ++j)
                    acc[i][j] += ar[i] * br[j];
        }
        __syncthreads();
    }

    const int cc = col0 + (tx << 2);
    float4 bi = *reinterpret_cast<const float4*>(&bias[cc]);
#pragma unroll
    for (int i = 0; i < 4; ++i) {
        int r = row0 + (ty << 2) + i;
        float4 o;
        o.x = acc[i][0] + bi.x;
        o.y = acc[i][1] + bi.y;
        o.z = acc[i][2] + bi.z;
        o.w = acc[i][3] + bi.w;
        *reinterpret_cast<float4*>(&C[(size_t)r * N + cc]) = o;
    }
}

// ---------------------------------------------------------------------------
// Causal flash attention.
// Layout: Q/K/V/O are [B, S, E] with head h at columns [h*D, h*D+D).
// One block = 128 q-rows of one (b,h). One thread owns one full q-row:
// q-row + output accumulator live in registers; online softmax is
// thread-private (no cross-thread reduction). K/V tiles (64 rows) stream
// through smem and are read with broadcast LDS.128 (conflict-free).
// ---------------------------------------------------------------------------
#define ABM 128   // q rows per block (== blockDim.x)
#define ABK 64    // kv rows per tile
#define APAD 68   // smem row stride in floats (272B: 16B-aligned, conflict-safe)

#define ATTN_SMEM_FLOATS (ABM * APAD + 2 * ABK * APAD)
#define ATTN_SMEM_BYTES  (ATTN_SMEM_FLOATS * 4)

__global__ __launch_bounds__(128) void attn_kernel(
    const float* __restrict__ Q, const float* __restrict__ K,
    const float* __restrict__ V, float* __restrict__ O)
{
    extern __shared__ float sm[];
    float (*Qs)[APAD] = reinterpret_cast<float (*)[APAD]>(sm);
    float (*Ks)[APAD] = reinterpret_cast<float (*)[APAD]>(sm + ABM * APAD);
    float (*Vs)[APAD] = reinterpret_cast<float (*)[APAD]>(sm + ABM * APAD + ABK * APAD);

    const int tid = threadIdx.x;
    const int qt  = blockIdx.x;
    const int bh  = blockIdx.y;
    const int b   = bh >> 4;          // / PH
    const int h   = bh & 15;          // % PH
    const size_t base = ((size_t)b * PS) * PE + (size_t)h * PD;
    const int q0  = qt * ABM;

    // Stage Q tile coalesced through smem, then copy own row to registers.
    for (int i = tid; i < ABM * (PD / 4); i += ABM) {
        int r  = i >> 4;
        int d4 = (i & 15) << 2;
        float4 v4 = *reinterpret_cast<const float4*>(
            &Q[base + (size_t)(q0 + r) * PE + d4]);
        Qs[r][d4 + 0] = v4.x; Qs[r][d4 + 1] = v4.y;
        Qs[r][d4 + 2] = v4.z; Qs[r][d4 + 3] = v4.w;
    }
    __syncthreads();

    float q[PD];
#pragma unroll
    for (int d = 0; d < PD; ++d) q[d] = Qs[tid][d] * 0.125f;  // fold 1/sqrt(D)

    float outv[PD];
#pragma unroll
    for (int d = 0; d < PD; ++d) outv[d] = 0.f;
    float m = -1e30f, l = 0.f;
    const int qrow = q0 + tid;
    const int kend = q0 + ABM;   // causal: only tiles up to this block's diagonal

#pragma unroll 1
    for (int j0 = 0; j0 < kend; j0 += ABK) {
        __syncthreads();
        // Cooperative K/V tile load (64 rows x 64 cols, float4-coalesced)
        for (int i = tid; i < ABK * (PD / 4); i += ABM) {
            int r  = i >> 4;
            int d4 = (i & 15) << 2;
            size_t g = base + (size_t)(j0 + r) * PE + d4;
            float4 kv = *reinterpret_cast<const float4*>(&K[g]);
            Ks[r][d4 + 0] = kv.x; Ks[r][d4 + 1] = kv.y;
            Ks[r][d4 + 2] = kv.z; Ks[r][d4 + 3] = kv.w;
            float4 vv = *reinterpret_cast<const float4*>(&V[g]);
            Vs[r][d4 + 0] = vv.x; Vs[r][d4 + 1] = vv.y;
            Vs[r][d4 + 2] = vv.z; Vs[r][d4 + 3] = vv.w;
        }
        __syncthreads();

#pragma unroll 1
        for (int kk0 = 0; kk0 < ABK; kk0 += 8) {
            // 8 concurrent dot products (ILP), broadcast smem reads
            float s[8];
#pragma unroll
            for (int u = 0; u < 8; ++u) s[u] = 0.f;
#pragma unroll
            for (int d = 0; d < PD; d += 4) {
#pragma unroll
                for (int u = 0; u < 8; ++u) {
                    float4 kv = *reinterpret_cast<const float4*>(&Ks[kk0 + u][d]);
                    s[u] += q[d] * kv.x + q[d + 1] * kv.y
                          + q[d + 2] * kv.z + q[d + 3] * kv.w;
                }
            }
            // causal mask
#pragma unroll
            for (int u = 0; u < 8; ++u) {
                int kg = j0 + kk0 + u;
                if (kg > qrow) s[u] = -1e30f;
            }
            // online softmax update (thread-private)
            float mt = s[0];
#pragma unroll
            for (int u = 1; u < 8; ++u) mt = fmaxf(mt, s[u]);
            float mnew = fmaxf(m, mt);
            float corr = __expf(m - mnew);
            float p[8];
            float psum = 0.f;
#pragma unroll
            for (int u = 0; u < 8; ++u) { p[u] = __expf(s[u] - mnew); psum += p[u]; }
            l = l * corr + psum;
            m = mnew;
#pragma unroll
            for (int d = 0; d < PD; ++d) outv[d] *= corr;
#pragma unroll
            for (int u = 0; u < 8; ++u) {
#pragma unroll
                for (int d = 0; d < PD; d += 4) {
                    float4 vv = *reinterpret_cast<const float4*>(&Vs[kk0 + u][d]);
                    outv[d]     += p[u] * vv.x;
                    outv[d + 1] += p[u] * vv.y;
                    outv[d + 2] += p[u] * vv.z;
                    outv[d + 3] += p[u] * vv.w;
                }
            }
        }
    }

    const float inv = 1.f / l;
    __syncthreads();
#pragma unroll
    for (int d = 0; d < PD; ++d) Qs[tid][d] = outv[d] * inv;
    __syncthreads();
    for (int i = tid; i < ABM * (PD / 4); i += ABM) {
        int r  = i >> 4;
        int d4 = (i & 15) << 2;
        float4 o4;
        o4.x = Qs[r][d4 + 0]; o4.y = Qs[r][d4 + 1];
        o4.z = Qs[r][d4 + 2]; o4.w = Qs[r][d4 + 3];
        *reinterpret_cast<float4*>(&O[base + (size_t)(q0 + r) * PE + d4]) = o4;
    }
}

// ---------------------------------------------------------------------------
extern "C" void kernel_launch(void* const* d_in, const int* in_sizes, int n_in,
                              void* d_out, int out_size)
{
    const float* x  = (const float*)d_in[0];
    const float* Wq = (const float*)d_in[1];
    const float* bq = (const float*)d_in[2];
    const float* Wk = (const float*)d_in[3];
    const float* bk = (const float*)d_in[4];
    const float* Wv = (const float*)d_in[5];
    const float* bv = (const float*)d_in[6];
    const float* Wo = (const float*)d_in[7];
    const float* bo = (const float*)d_in[8];
    float* out = (float*)d_out;

    float *Qp, *Kp, *Vp, *AOp;
    cudaGetSymbolAddress((void**)&Qp,  g_Q);
    cudaGetSymbolAddress((void**)&Kp,  g_K);
    cudaGetSymbolAddress((void**)&Vp,  g_V);
    cudaGetSymbolAddress((void**)&AOp, g_AO);

    cudaFuncSetAttribute(attn_kernel,
                         cudaFuncAttributeMaxDynamicSharedMemorySize,
                         ATTN_SMEM_BYTES);

    dim3 gGrid(PE / GBN, PBS / GBM);   // (16, 64)
    gemm_bias_kernel<<<gGrid, 256>>>(x, Wq, bq, Qp, PBS, PE, PE);
    gemm_bias_kernel<<<gGrid, 256>>>(x, Wk, bk, Kp, PBS, PE, PE);
    gemm_bias_kernel<<<gGrid, 256>>>(x, Wv, bv, Vp, PBS, PE, PE);

    attn_kernel<<<dim3(PS / ABM, PB * PH), ABM, ATTN_SMEM_BYTES>>>(Qp, Kp, Vp, AOp);

    gemm_bias_kernel<<<gGrid, 256>>>(AOp, Wo, bo, out, PBS, PE, PE);
}